// round 1
// baseline (speedup 1.0000x reference)
#include <cuda_runtime.h>
#include <cuda_bf16.h>

// ---------------------------------------------------------------------------
// GraphAutoencoder: scatter-mean (SAGE) -> fused encoder GEMM -> decoder GEMM
// Round 1 baseline: fp32 tiled SGEMM + float4 global atomics for the scatter.
// ---------------------------------------------------------------------------

#define N_NODES_MAX 50000
#define IN_DIM      256
#define HID_DIM     512
#define OUT_DIM     256

// Scratch (allocation-free rule: __device__ globals)
__device__ __align__(16) float4 g_neigh4[N_NODES_MAX * (IN_DIM / 4)];   // 51.2 MB
__device__ float g_deg[N_NODES_MAX];
__device__ float g_inv[N_NODES_MAX];
__device__ __align__(16) float g_h_fallback[N_NODES_MAX * HID_DIM];    // 102 MB (only used if out layout differs)

// ---------------------------------------------------------------------------
// Zero scratch
// ---------------------------------------------------------------------------
__global__ void zero_kernel(int n_nodes) {
    int total4 = n_nodes * (IN_DIM / 4);
    for (int i = blockIdx.x * blockDim.x + threadIdx.x; i < total4;
         i += gridDim.x * blockDim.x) {
        g_neigh4[i] = make_float4(0.f, 0.f, 0.f, 0.f);
        if (i < n_nodes) g_deg[i] = 0.f;
    }
}

// ---------------------------------------------------------------------------
// Degree accumulation (1 thread / edge)
// ---------------------------------------------------------------------------
__global__ void deg_kernel(const int* __restrict__ dst, int n_edges) {
    int i = blockIdx.x * blockDim.x + threadIdx.x;
    if (i < n_edges) atomicAdd(&g_deg[dst[i]], 1.0f);
}

// ---------------------------------------------------------------------------
// Feature scatter: item = (edge, chunk-of-float4). A warp covers 32 chunks of
// one edge -> broadcast src/dst loads, fully coalesced x reads, float4 atomics.
// ---------------------------------------------------------------------------
__global__ void scatter_kernel(const float* __restrict__ x,
                               const int* __restrict__ src,
                               const int* __restrict__ dst,
                               int n_edges) {
    const int CH = IN_DIM / 4;  // 64 float4 per edge
    long long total = (long long)n_edges * CH;
    long long i = (long long)blockIdx.x * blockDim.x + threadIdx.x;
    if (i >= total) return;
    int e = (int)(i >> 6);
    int c = (int)(i & 63);
    int s = src[e];
    int d = dst[e];
    float4 v = reinterpret_cast<const float4*>(x)[(long long)s * CH + c];
#if __CUDA_ARCH__ >= 900
    atomicAdd(&g_neigh4[(long long)d * CH + c], v);
#else
    float* p = reinterpret_cast<float*>(&g_neigh4[(long long)d * CH + c]);
    atomicAdd(p + 0, v.x); atomicAdd(p + 1, v.y);
    atomicAdd(p + 2, v.z); atomicAdd(p + 3, v.w);
#endif
}

// ---------------------------------------------------------------------------
// inv_deg = 1 / max(deg, 1)
// ---------------------------------------------------------------------------
__global__ void inv_kernel(int n_nodes) {
    int i = blockIdx.x * blockDim.x + threadIdx.x;
    if (i < n_nodes) g_inv[i] = 1.0f / fmaxf(g_deg[i], 1.0f);
}

// ---------------------------------------------------------------------------
// Tiled SGEMM: C[M,N] = act( A1[M,K]@B1[K,N] (+ (inv*A2)[M,K]@B2[K,N]) + bias )
// BM=BN=128, BK=8, 256 threads, 8x8 per thread, float4 smem paths.
// TWO_PHASE: encoder (x@W_self + neigh_mean@W_neigh). RELU: encoder only.
// ---------------------------------------------------------------------------
template <bool RELU, bool TWO_PHASE>
__launch_bounds__(256, 1)
__global__ void gemm_kernel(const float* __restrict__ A1,
                            const float* __restrict__ B1,
                            const float* __restrict__ A2,
                            const float* __restrict__ B2,
                            const float* __restrict__ bias,
                            float* __restrict__ C,
                            int M, int K, int N) {
    const int BM = 128, BN = 128, BK = 8;
    __shared__ float As[BK][BM];
    __shared__ float Bs[BK][BN];

    int tid = threadIdx.x;
    int rowBase = blockIdx.y * BM;
    int colBase = blockIdx.x * BN;

    int aRow = tid >> 1;           // 0..127
    int aCol = (tid & 1) * 4;      // 0 or 4
    int bRow = tid >> 5;           // 0..7
    int bCol = (tid & 31) * 4;     // 0..124

    int tRow = (tid >> 4) * 8;     // 0..120
    int tCol = (tid & 15) * 8;     // 0..120

    float acc[8][8];
#pragma unroll
    for (int i = 0; i < 8; i++)
#pragma unroll
        for (int j = 0; j < 8; j++) acc[i][j] = 0.f;

    int gRowA = rowBase + aRow;
    const int nPhases = TWO_PHASE ? 2 : 1;

    for (int ph = 0; ph < nPhases; ph++) {
        const float* __restrict__ A = (TWO_PHASE && ph) ? A2 : A1;
        const float* __restrict__ B = (TWO_PHASE && ph) ? B2 : B1;
        float scale = 1.0f;
        if (TWO_PHASE && ph) scale = (gRowA < M) ? g_inv[gRowA] : 0.f;

        for (int k0 = 0; k0 < K; k0 += BK) {
            float4 av = make_float4(0.f, 0.f, 0.f, 0.f);
            if (gRowA < M)
                av = *reinterpret_cast<const float4*>(
                    &A[(long long)gRowA * K + k0 + aCol]);
            if (TWO_PHASE && ph) {
                av.x *= scale; av.y *= scale; av.z *= scale; av.w *= scale;
            }
            As[aCol + 0][aRow] = av.x;
            As[aCol + 1][aRow] = av.y;
            As[aCol + 2][aRow] = av.z;
            As[aCol + 3][aRow] = av.w;

            float4 bv = *reinterpret_cast<const float4*>(
                &B[(long long)(k0 + bRow) * N + colBase + bCol]);
            *reinterpret_cast<float4*>(&Bs[bRow][bCol]) = bv;

            __syncthreads();

#pragma unroll
            for (int k = 0; k < BK; k++) {
                float4 a0 = *reinterpret_cast<const float4*>(&As[k][tRow]);
                float4 a1 = *reinterpret_cast<const float4*>(&As[k][tRow + 4]);
                float4 b0 = *reinterpret_cast<const float4*>(&Bs[k][tCol]);
                float4 b1 = *reinterpret_cast<const float4*>(&Bs[k][tCol + 4]);
                float ar[8] = {a0.x, a0.y, a0.z, a0.w, a1.x, a1.y, a1.z, a1.w};
                float br[8] = {b0.x, b0.y, b0.z, b0.w, b1.x, b1.y, b1.z, b1.w};
#pragma unroll
                for (int i = 0; i < 8; i++)
#pragma unroll
                    for (int j = 0; j < 8; j++)
                        acc[i][j] += ar[i] * br[j];
            }
            __syncthreads();
        }
    }

    // epilogue: bias (+relu), vectorized stores
#pragma unroll
    for (int i = 0; i < 8; i++) {
        int r = rowBase + tRow + i;
        if (r >= M) continue;
#pragma unroll
        for (int j = 0; j < 8; j += 4) {
            int c = colBase + tCol + j;
            float4 v;
            v.x = acc[i][j + 0] + bias[c + 0];
            v.y = acc[i][j + 1] + bias[c + 1];
            v.z = acc[i][j + 2] + bias[c + 2];
            v.w = acc[i][j + 3] + bias[c + 3];
            if (RELU) {
                v.x = fmaxf(v.x, 0.f); v.y = fmaxf(v.y, 0.f);
                v.z = fmaxf(v.z, 0.f); v.w = fmaxf(v.w, 0.f);
            }
            *reinterpret_cast<float4*>(&C[(long long)r * N + c]) = v;
        }
    }
}

// ---------------------------------------------------------------------------
// Launch
// ---------------------------------------------------------------------------
extern "C" void kernel_launch(void* const* d_in, const int* in_sizes, int n_in,
                              void* d_out, int out_size) {
    const float* x       = (const float*)d_in[0];
    const int*   src     = (const int*)d_in[1];
    const int*   dst     = (const int*)d_in[2];
    const float* W_self  = (const float*)d_in[3];
    const float* W_neigh = (const float*)d_in[4];
    const float* b_enc   = (const float*)d_in[5];
    const float* W_dec   = (const float*)d_in[6];
    const float* b_dec   = (const float*)d_in[7];

    int M  = in_sizes[0] / IN_DIM;   // 50000
    int nE = in_sizes[1];            // 800000

    float* out = (float*)d_out;
    float* h;
    if (out_size == M * (OUT_DIM + HID_DIM)) {
        h = out + (long long)M * OUT_DIM;       // tuple layout: (recon, h)
    } else {
        void* p = nullptr;
        cudaGetSymbolAddress(&p, g_h_fallback);
        h = (float*)p;
    }

    void* pneigh = nullptr;
    cudaGetSymbolAddress(&pneigh, g_neigh4);
    const float* neigh = (const float*)pneigh;

    // 1) zero scratch
    {
        int total4 = M * (IN_DIM / 4);
        int blocks = (total4 + 255) / 256;
        zero_kernel<<<blocks, 256>>>(M);
    }
    // 2) degrees + feature scatter
    deg_kernel<<<(nE + 255) / 256, 256>>>(dst, nE);
    {
        long long items = (long long)nE * (IN_DIM / 4);
        int blocks = (int)((items + 255) / 256);
        scatter_kernel<<<blocks, 256>>>(x, src, dst, nE);
    }
    // 3) inverse degree
    inv_kernel<<<(M + 255) / 256, 256>>>(M);

    // 4) encoder: h = relu(x@W_self + (neigh*inv)@W_neigh + b_enc)
    {
        dim3 grid(HID_DIM / 128, (M + 127) / 128);
        gemm_kernel<true, true><<<grid, 256>>>(x, W_self, neigh, W_neigh,
                                               b_enc, h, M, IN_DIM, HID_DIM);
    }
    // 5) decoder: recon = h@W_dec + b_dec
    {
        dim3 grid(OUT_DIM / 128, (M + 127) / 128);
        gemm_kernel<false, false><<<grid, 256>>>(h, W_dec, nullptr, nullptr,
                                                 b_dec, out, M, HID_DIM, OUT_DIM);
    }
}

// round 3
// speedup vs baseline: 1.7771x; 1.7771x over previous
#include <cuda_runtime.h>
#include <cuda_bf16.h>
#include <cstdint>

// ---------------------------------------------------------------------------
// GraphAutoencoder on sm_100 (base, no tcgen05):
// scatter-mean -> encoder GEMM -> decoder GEMM, GEMMs via mma.sync bf16
// with two-term split (hh + hi*lo + lo*hi), fp32 accumulate. K' = 3*512.
// ---------------------------------------------------------------------------

#define N_NODES_MAX 50000
#define IN_DIM      256
#define HID_DIM     512
#define OUT_DIM     256
#define KP          1536
#define NCH         48           // KP / 32

// ------------------------------ scratch ------------------------------------
__device__ __align__(16) float g_neigh[N_NODES_MAX * IN_DIM];
__device__ float g_deg[N_NODES_MAX];
__device__ float g_inv[N_NODES_MAX];
// combined encoder A: [x | neigh_mean], hi/lo split, stride 512
__device__ __align__(16) __nv_bfloat16 g_eAh[N_NODES_MAX * 512];
__device__ __align__(16) __nv_bfloat16 g_eAl[N_NODES_MAX * 512];
// h split (decoder A), stride 512
__device__ __align__(16) __nv_bfloat16 g_hh[N_NODES_MAX * HID_DIM];
__device__ __align__(16) __nv_bfloat16 g_hl[N_NODES_MAX * HID_DIM];
// packed B: [KP][N] row-major
__device__ __align__(16) __nv_bfloat16 g_Benc[KP * HID_DIM];
__device__ __align__(16) __nv_bfloat16 g_Bdec[KP * OUT_DIM];
__device__ __align__(16) float g_hfb[N_NODES_MAX * HID_DIM];

// --------------------------- asm helpers -----------------------------------
__device__ __forceinline__ uint32_t smem_u32(const void* p) {
    uint32_t a;
    asm("{ .reg .u64 t; cvta.to.shared.u64 t, %1; cvt.u32.u64 %0, t; }"
        : "=r"(a) : "l"(p));
    return a;
}
__device__ __forceinline__ void cp16(uint32_t dst, const void* src, uint32_t srcsize) {
    asm volatile("cp.async.cg.shared.global [%0], [%1], 16, %2;"
                 :: "r"(dst), "l"(src), "r"(srcsize) : "memory");
}
__device__ __forceinline__ void cp_commit() {
    asm volatile("cp.async.commit_group;" ::: "memory");
}
template <int N>
__device__ __forceinline__ void cp_wait() {
    asm volatile("cp.async.wait_group %0;" :: "n"(N) : "memory");
}
#define LDSM_X4(r0, r1, r2, r3, a) \
    asm volatile("ldmatrix.sync.aligned.m8n8.x4.shared.b16 {%0,%1,%2,%3}, [%4];" \
                 : "=r"(r0), "=r"(r1), "=r"(r2), "=r"(r3) : "r"(a))
#define LDSM_X4_T(r0, r1, r2, r3, a) \
    asm volatile("ldmatrix.sync.aligned.m8n8.x4.trans.shared.b16 {%0,%1,%2,%3}, [%4];" \
                 : "=r"(r0), "=r"(r1), "=r"(r2), "=r"(r3) : "r"(a))
#define MMA16816(c, a0, a1, a2, a3, b0, b1) \
    asm volatile("mma.sync.aligned.m16n8k16.row.col.f32.bf16.bf16.f32 " \
                 "{%0,%1,%2,%3}, {%4,%5,%6,%7}, {%8,%9}, {%0,%1,%2,%3};" \
                 : "+f"((c)[0]), "+f"((c)[1]), "+f"((c)[2]), "+f"((c)[3]) \
                 : "r"(a0), "r"(a1), "r"(a2), "r"(a3), "r"(b0), "r"(b1))

// ----------------------------- prep kernels --------------------------------
__global__ void prep0_kernel(const float* __restrict__ x, int M) {
    int i = blockIdx.x * blockDim.x + threadIdx.x;
    if (i >= M * IN_DIM) return;
    g_neigh[i] = 0.f;
    int r = i >> 8, c = i & 255;
    float v = x[i];
    __nv_bfloat16 hi = __float2bfloat16(v);
    g_eAh[(size_t)r * 512 + c] = hi;
    g_eAl[(size_t)r * 512 + c] = __float2bfloat16(v - __bfloat162float(hi));
    if (i < M) g_deg[i] = 0.f;
}

__global__ void deg_kernel(const int* __restrict__ dst, int n_edges) {
    int i = blockIdx.x * blockDim.x + threadIdx.x;
    if (i < n_edges) atomicAdd(&g_deg[dst[i]], 1.0f);
}

__global__ void scatter_kernel(const float* __restrict__ x,
                               const int* __restrict__ src,
                               const int* __restrict__ dst,
                               int n_edges) {
    const int CH = IN_DIM / 4;
    long long total = (long long)n_edges * CH;
    long long i = (long long)blockIdx.x * blockDim.x + threadIdx.x;
    if (i >= total) return;
    int e = (int)(i >> 6), c = (int)(i & 63);
    int s = src[e], d = dst[e];
    float4 v = reinterpret_cast<const float4*>(x)[(long long)s * CH + c];
    atomicAdd(reinterpret_cast<float4*>(g_neigh) + (long long)d * CH + c, v);
}

__global__ void inv_kernel(int M) {
    int i = blockIdx.x * blockDim.x + threadIdx.x;
    if (i < M) g_inv[i] = 1.0f / fmaxf(g_deg[i], 1.0f);
}

// neigh mean split into combined A + B packing, one launch
__global__ void prep1_kernel(const float* __restrict__ Wself,
                             const float* __restrict__ Wneigh,
                             const float* __restrict__ Wdec, int M) {
    int i = blockIdx.x * blockDim.x + threadIdx.x;
    int nx = M * IN_DIM;
    if (i < nx) {
        int r = i >> 8, c = i & 255;
        float v = g_neigh[i] * g_inv[r];
        __nv_bfloat16 hi = __float2bfloat16(v);
        g_eAh[(size_t)r * 512 + 256 + c] = hi;
        g_eAl[(size_t)r * 512 + 256 + c] = __float2bfloat16(v - __bfloat162float(hi));
        return;
    }
    int j = i - nx;
    if (j < KP * HID_DIM) {
        int kp = j >> 9, n = j & 511;         // HID_DIM = 512
        int seg = kp >> 9, k = kp & 511;
        float w = (k < 256) ? Wself[k * HID_DIM + n] : Wneigh[(k - 256) * HID_DIM + n];
        __nv_bfloat16 hi = __float2bfloat16(w);
        g_Benc[j] = (seg == 1) ? __float2bfloat16(w - __bfloat162float(hi)) : hi;
        return;
    }
    j -= KP * HID_DIM;
    if (j < KP * OUT_DIM) {
        int kp = j >> 8, n = j & 255;         // OUT_DIM = 256
        int seg = kp >> 9, k = kp & 511;
        float w = Wdec[k * OUT_DIM + n];
        __nv_bfloat16 hi = __float2bfloat16(w);
        g_Bdec[j] = (seg == 1) ? __float2bfloat16(w - __bfloat162float(hi)) : hi;
    }
}

// ----------------------------- mma GEMM ------------------------------------
// C[M,N] = act( A'[M,KP] @ B[KP,N] + bias ), A' = split-expanded A.
// CTA tile 128x128, 8 warps (4 M x 2 N), warp tile 32x64, BK=32.
#define A_PITCH 80           // (32+8) bf16 per row
#define B_PITCH 272          // (128+8) bf16 per row
#define SZA (128 * A_PITCH)  // 10240 B per buffer
#define SZB (32 * B_PITCH)   // 8704 B per buffer

template <bool RELU, bool SPLIT>
__global__ __launch_bounds__(256, 2)
void gemm_mma(const __nv_bfloat16* __restrict__ Ah,
              const __nv_bfloat16* __restrict__ Al,
              const __nv_bfloat16* __restrict__ Bp,
              const float* __restrict__ bias,
              float* __restrict__ C,
              __nv_bfloat16* __restrict__ oH, __nv_bfloat16* __restrict__ oL,
              int M, int N) {
    __shared__ __align__(16) unsigned char smA[2 * SZA];
    __shared__ __align__(16) unsigned char smB[2 * SZB];
    uint32_t sA = smem_u32(smA), sB = smem_u32(smB);

    int tid = threadIdx.x;
    int wid = tid >> 5, lane = tid & 31;
    int wm = wid & 3, wn = wid >> 2;
    int rowBase = blockIdx.y * 128;
    int colBase = blockIdx.x * 128;

    float c[2][8][4];
#pragma unroll
    for (int f = 0; f < 2; f++)
#pragma unroll
        for (int nf = 0; nf < 8; nf++)
#pragma unroll
            for (int q = 0; q < 4; q++) c[f][nf][q] = 0.f;

    // ---- load helper (as lambda) ----
    auto load_chunk = [&](int buf, int ch) {
        int seg = ch >> 4;
        const __nv_bfloat16* Asel = (seg < 2) ? Ah : Al;
        int k0 = (ch * 32) & 511;
        int kp0 = ch * 32;
#pragma unroll
        for (int i = 0; i < 2; i++) {
            int idx = tid + i * 256;
            int r = idx >> 2, cs = idx & 3;
            int grow = rowBase + r;
            int srow = grow < M ? grow : M - 1;
            cp16(sA + buf * SZA + r * A_PITCH + cs * 16,
                 Asel + (size_t)srow * 512 + k0 + cs * 8,
                 grow < M ? 16u : 0u);
        }
#pragma unroll
        for (int i = 0; i < 2; i++) {
            int idx = tid + i * 256;
            int r = idx >> 4, cs = idx & 15;
            cp16(sB + buf * SZB + r * B_PITCH + cs * 16,
                 Bp + (size_t)(kp0 + r) * N + colBase + cs * 8, 16u);
        }
        cp_commit();
    };

    // lane-invariant smem ldmatrix addresses
    uint32_t aAddr = sA + (wm * 32 + (lane & 15)) * A_PITCH + (lane >> 4) * 16;
    uint32_t bAddr = sB + (lane & 15) * B_PITCH + wn * 128 + (lane >> 4) * 16;

    load_chunk(0, 0);
    for (int ch = 0; ch < NCH; ch++) {
        int buf = ch & 1;
        if (ch + 1 < NCH) { load_chunk(buf ^ 1, ch + 1); cp_wait<1>(); }
        else              { cp_wait<0>(); }
        __syncthreads();

        uint32_t aB = aAddr + buf * SZA;
        uint32_t bB = bAddr + buf * SZB;
#pragma unroll
        for (int kk = 0; kk < 2; kk++) {
            uint32_t a[8];
            LDSM_X4(a[0], a[1], a[2], a[3], aB + kk * 32);
            LDSM_X4(a[4], a[5], a[6], a[7], aB + kk * 32 + 16 * A_PITCH);
            uint32_t b[16];
#pragma unroll
            for (int p = 0; p < 4; p++)
                LDSM_X4_T(b[4 * p], b[4 * p + 1], b[4 * p + 2], b[4 * p + 3],
                          bB + kk * 16 * B_PITCH + p * 32);
#pragma unroll
            for (int f = 0; f < 2; f++)
#pragma unroll
                for (int nf = 0; nf < 8; nf++) {
                    uint32_t* bp = b + (nf >> 1) * 4 + (nf & 1) * 2;
                    MMA16816(c[f][nf], a[f * 4], a[f * 4 + 1], a[f * 4 + 2],
                             a[f * 4 + 3], bp[0], bp[1]);
                }
        }
        __syncthreads();
    }

    // ---- epilogue ----
    int groupID = lane >> 2, tid4 = lane & 3;
#pragma unroll
    for (int f = 0; f < 2; f++) {
        int r0 = rowBase + wm * 32 + f * 16 + groupID;
#pragma unroll
        for (int nf = 0; nf < 8; nf++) {
            int cb = colBase + wn * 64 + nf * 8 + tid4 * 2;
            float b0 = bias[cb], b1 = bias[cb + 1];
#pragma unroll
            for (int h = 0; h < 2; h++) {
                int r = r0 + h * 8;
                if (r >= M) continue;
                float v0 = c[f][nf][2 * h + 0] + b0;
                float v1 = c[f][nf][2 * h + 1] + b1;
                if (RELU) { v0 = fmaxf(v0, 0.f); v1 = fmaxf(v1, 0.f); }
                float2 v = make_float2(v0, v1);
                *reinterpret_cast<float2*>(C + (size_t)r * N + cb) = v;
                if (SPLIT) {
                    __nv_bfloat16 h0 = __float2bfloat16(v0);
                    __nv_bfloat16 h1 = __float2bfloat16(v1);
                    __nv_bfloat162 hv; hv.x = h0; hv.y = h1;
                    *reinterpret_cast<__nv_bfloat162*>(oH + (size_t)r * N + cb) = hv;
                    __nv_bfloat162 lv;
                    lv.x = __float2bfloat16(v0 - __bfloat162float(h0));
                    lv.y = __float2bfloat16(v1 - __bfloat162float(h1));
                    *reinterpret_cast<__nv_bfloat162*>(oL + (size_t)r * N + cb) = lv;
                }
            }
        }
    }
}

// ------------------------------ launch -------------------------------------
extern "C" void kernel_launch(void* const* d_in, const int* in_sizes, int n_in,
                              void* d_out, int out_size) {
    const float* x       = (const float*)d_in[0];
    const int*   src     = (const int*)d_in[1];
    const int*   dst     = (const int*)d_in[2];
    const float* W_self  = (const float*)d_in[3];
    const float* W_neigh = (const float*)d_in[4];
    const float* b_enc   = (const float*)d_in[5];
    const float* W_dec   = (const float*)d_in[6];
    const float* b_dec   = (const float*)d_in[7];

    int M  = in_sizes[0] / IN_DIM;
    int nE = in_sizes[1];

    float* out = (float*)d_out;
    float* h;
    if (out_size == M * (OUT_DIM + HID_DIM)) {
        h = out + (long long)M * OUT_DIM;
    } else {
        void* p = nullptr;
        cudaGetSymbolAddress(&p, g_hfb);
        h = (float*)p;
    }

    void *p_eAh, *p_eAl, *p_hh, *p_hl, *p_be, *p_bd;
    cudaGetSymbolAddress(&p_eAh, g_eAh); cudaGetSymbolAddress(&p_eAl, g_eAl);
    cudaGetSymbolAddress(&p_hh, g_hh);   cudaGetSymbolAddress(&p_hl, g_hl);
    cudaGetSymbolAddress(&p_be, g_Benc); cudaGetSymbolAddress(&p_bd, g_Bdec);

    // 1) zero neigh/deg + split x into combined A
    prep0_kernel<<<(M * IN_DIM + 255) / 256, 256>>>(x, M);
    // 2) degrees
    deg_kernel<<<(nE + 255) / 256, 256>>>(dst, nE);
    // 3) feature scatter
    {
        long long items = (long long)nE * (IN_DIM / 4);
        scatter_kernel<<<(int)((items + 255) / 256), 256>>>(x, src, dst, nE);
    }
    // 4) inverse degree
    inv_kernel<<<(M + 255) / 256, 256>>>(M);
    // 5) neigh-mean split + weight packing
    {
        int total = M * IN_DIM + KP * HID_DIM + KP * OUT_DIM;
        prep1_kernel<<<(total + 255) / 256, 256>>>(W_self, W_neigh, W_dec, M);
    }
    // 6) encoder GEMM: h = relu(A' @ Benc + b_enc), also emit h split
    {
        dim3 grid(HID_DIM / 128, (M + 127) / 128);
        gemm_mma<true, true><<<grid, 256>>>(
            (const __nv_bfloat16*)p_eAh, (const __nv_bfloat16*)p_eAl,
            (const __nv_bfloat16*)p_be, b_enc, h,
            (__nv_bfloat16*)p_hh, (__nv_bfloat16*)p_hl, M, HID_DIM);
    }
    // 7) decoder GEMM: out = h' @ Bdec + b_dec
    {
        dim3 grid(OUT_DIM / 128, (M + 127) / 128);
        gemm_mma<false, false><<<grid, 256>>>(
            (const __nv_bfloat16*)p_hh, (const __nv_bfloat16*)p_hl,
            (const __nv_bfloat16*)p_bd, b_dec, out,
            nullptr, nullptr, M, OUT_DIM);
    }
}